// round 6
// baseline (speedup 1.0000x reference)
#include <cuda_runtime.h>
#include <cstdint>

// Problem constants (fixed by dataset).
#define N_NODES   400000
#define N_GRAPHS  1000
#define FEAT      240     // 64*1 + 32*3 + 16*5
#define NINST     112     // 64 + 32 + 16 irrep instances
#define NPAD      128     // NINST padded to power of 2 for cheap task decode
#define NB        8       // nodes staged per tile in pooling kernel

// ---------------------------------------------------------------------------
// Scratch (static device globals — no allocation allowed).
// ---------------------------------------------------------------------------
__device__ int g_counts[N_GRAPHS];
__device__ int g_offs[N_GRAPHS + 1];
__device__ int g_cursor[N_GRAPHS];
__device__ int g_perm[N_NODES];

// ---------------------------------------------------------------------------
// K0: zero counters (runs every replay — graph-capture safe, deterministic)
// ---------------------------------------------------------------------------
__global__ void k_zero()
{
    int i = blockIdx.x * blockDim.x + threadIdx.x;
    if (i < N_GRAPHS) g_counts[i] = 0;
}

// ---------------------------------------------------------------------------
// K1: histogram of graph indices
// ---------------------------------------------------------------------------
__global__ void k_hist(const int* __restrict__ index)
{
    int i = blockIdx.x * blockDim.x + threadIdx.x;
    if (i < N_NODES) atomicAdd(&g_counts[index[i]], 1);
}

// ---------------------------------------------------------------------------
// K2: exclusive scan over 1000 counts (single block, Hillis-Steele)
// ---------------------------------------------------------------------------
__global__ void k_scan()
{
    __shared__ int s[1024];
    int tid = threadIdx.x;
    int c = (tid < N_GRAPHS) ? g_counts[tid] : 0;
    s[tid] = c;
    __syncthreads();
    #pragma unroll
    for (int off = 1; off < 1024; off <<= 1) {
        int v = (tid >= off) ? s[tid - off] : 0;
        __syncthreads();
        s[tid] += v;
        __syncthreads();
    }
    if (tid < N_GRAPHS) {
        int excl = s[tid] - c;
        g_offs[tid]   = excl;
        g_cursor[tid] = excl;
    }
    if (tid == 0) g_offs[N_GRAPHS] = s[N_GRAPHS - 1];
}

// ---------------------------------------------------------------------------
// K3: scatter nodes into per-graph contiguous segments (counting sort;
// intra-graph order is irrelevant — everything downstream is a sum)
// ---------------------------------------------------------------------------
__global__ void k_scatter(const int* __restrict__ index)
{
    int i = blockIdx.x * blockDim.x + threadIdx.x;
    if (i < N_NODES) {
        int g   = index[i];
        int pos = atomicAdd(&g_cursor[g], 1);
        g_perm[pos] = i;
    }
}

// ---------------------------------------------------------------------------
// K4: per-graph pooling + o3.Linear epilogue, fused. One CTA (256 th) per graph.
// Double-buffered, software-pipelined staging with perm-index look-ahead;
// register accumulators; zero global atomics; single streaming read of x.
// ---------------------------------------------------------------------------
__global__ __launch_bounds__(256) void k_pool(const float* __restrict__ x,
                                              const float* __restrict__ W0,
                                              const float* __restrict__ W1,
                                              const float* __restrict__ W2,
                                              const float* __restrict__ b0,
                                              float* __restrict__ out)
{
    const int g   = blockIdx.x;
    const int tid = threadIdx.x;
    const int beg = g_offs[g];
    const int end = g_offs[g + 1];
    const int cnt = end - beg;

    __shared__ float xs [2][NB][FEAT];   // double-buffered node tiles
    __shared__ float yps[NB][NPAD];      // exp(+norm), padded to 128 cols
    __shared__ float yms[NB][NPAD];      // exp(-norm)
    __shared__ float totY[2 * NINST];
    __shared__ float c[720];             // mean[240] | softmax[240] | softmin[240]

    // irrep instance owning feature t
    const int t  = tid;
    const int kt = (t < 64) ? t : (t < 160 ? 64 + (t - 64) / 3 : 96 + (t - 160) / 5);

    float accS = 0.f, accP = 0.f, accM = 0.f;   // per-feature sums   (t < 240)
    float accYp = 0.f, accYm = 0.f;             // per-instance sums  (t < 112)

    // staging decomposition: NB*60=480 float4 = 2 per thread (2nd masked >=480)
    const int j0 = tid / 60,         v0 = tid % 60;
    const int j1 = (tid + 256) / 60, v1 = (tid + 256) % 60;
    const bool has1 = (tid + 256) < NB * 60;

    const int nIter = (cnt + NB - 1) / NB;
    int cur = 0;

    // ---- prologue: load + stage tile 0; pre-load perm indices for tile 1 ----
    if (nIter > 0) {
        const int nv0 = min(NB, cnt);
        float4 a, b;
        bool l0 = (j0 < nv0);
        bool l1 = has1 && (j1 < nv0);
        if (l0) a = reinterpret_cast<const float4*>(x + (size_t)g_perm[beg + j0] * FEAT)[v0];
        if (l1) b = reinterpret_cast<const float4*>(x + (size_t)g_perm[beg + j1] * FEAT)[v1];
        if (l0) reinterpret_cast<float4*>(xs[0][j0])[v0] = a;
        if (l1) reinterpret_cast<float4*>(xs[0][j1])[v1] = b;
    }
    // perm look-ahead for tile 1 (addresses ready before iteration 0 starts)
    int np0 = 0, np1 = 0;
    bool npl0 = false, npl1 = false;
    if (nIter > 1) {
        const int nbase = beg + NB;
        const int nvn   = min(NB, end - nbase);
        npl0 = (j0 < nvn);
        npl1 = has1 && (j1 < nvn);
        if (npl0) np0 = g_perm[nbase + j0];
        if (npl1) np1 = g_perm[nbase + j1];
    }
    __syncthreads();

    for (int it = 0; it < nIter; it++) {
        const int base   = beg + it * NB;
        const int nvalid = min(NB, end - base);

        // ---- issue next-tile x prefetch immediately (addresses pre-loaded) ----
        float4 pa, pb;
        const bool pl0 = npl0, pl1 = npl1;
        if (pl0) pa = reinterpret_cast<const float4*>(x + (size_t)np0 * FEAT)[v0];
        if (pl1) pb = reinterpret_cast<const float4*>(x + (size_t)np1 * FEAT)[v1];

        // ---- pre-load perm indices for tile it+2 (independent LDG) ----
        npl0 = npl1 = false;
        if (it + 2 < nIter) {
            const int nbase = base + 2 * NB;
            const int nvn   = min(NB, end - nbase);
            npl0 = (j0 < nvn);
            npl1 = has1 && (j1 < nvn);
            if (npl0) np0 = g_perm[nbase + j0];
            if (npl1) np1 = g_perm[nbase + j1];
        }

        const float (*xc)[FEAT] = xs[cur];

        // ---- per-instance norms -> exp(+norm), 1/exp(+norm) ----
        // NB*NPAD = 1024 tasks / 256 threads = 4 per thread; shift/mask decode.
        #pragma unroll
        for (int r = 0; r < (NB * NPAD) / 256; r++) {
            int task = tid + r * 256;
            int j = task >> 7, k = task & (NPAD - 1);
            if (k < NINST && j < nvalid) {
                int s, d;
                if (k < 64)      { s = k;                  d = 1; }
                else if (k < 96) { s = 64 + 3 * (k - 64);  d = 3; }
                else             { s = 160 + 5 * (k - 96); d = 5; }
                float q = 0.f;
                #pragma unroll 5
                for (int e = 0; e < d; e++) { float u = xc[j][s + e]; q += u * u; }
                float ep = __expf(sqrtf(q));
                yps[j][k] = ep;
                yms[j][k] = __frcp_rn(ep);   // exp(-n) = 1/exp(n)
            }
        }
        __syncthreads();

        // ---- register accumulation (fast path for full tiles) ----
        if (nvalid == NB) {
            if (t < FEAT) {
                #pragma unroll
                for (int j = 0; j < NB; j++) {
                    float v = xc[j][t];
                    accS += v;
                    accP += v * yps[j][kt];
                    accM += v * yms[j][kt];
                }
            }
            if (t < NINST) {
                #pragma unroll
                for (int j = 0; j < NB; j++) { accYp += yps[j][t]; accYm += yms[j][t]; }
            }
        } else {
            if (t < FEAT) {
                for (int j = 0; j < nvalid; j++) {
                    float v = xc[j][t];
                    accS += v;
                    accP += v * yps[j][kt];
                    accM += v * yms[j][kt];
                }
            }
            if (t < NINST) {
                for (int j = 0; j < nvalid; j++) { accYp += yps[j][t]; accYm += yms[j][t]; }
            }
        }

        // ---- stage prefetched tile into the alternate buffer ----
        // (safe: buf[cur^1] was last read before the end barrier of it-1)
        if (pl0) reinterpret_cast<float4*>(xs[cur ^ 1][j0])[v0] = pa;
        if (pl1) reinterpret_cast<float4*>(xs[cur ^ 1][j1])[v1] = pb;
        __syncthreads();
        cur ^= 1;
    }

    if (t < NINST) { totY[t] = accYp; totY[NINST + t] = accYm; }
    __syncthreads();

    // ---- finalize pooled features into smem c[720] ----
    if (t < FEAT) {
        if (cnt == 0) {
            c[t] = 0.f; c[240 + t] = 0.f; c[480 + t] = 0.f;
        } else {
            c[t]       = accS / (float)cnt;
            c[240 + t] = accP / totY[kt];
            c[480 + t] = accM / totY[NINST + kt];
        }
    }
    __syncthreads();

    // ---- fused o3.Linear epilogue: thread t -> output feature t ----
    if (t >= FEAT) return;
    float acc = 0.f;

    if (t < 64) {
        // group 0e: cat[192] @ W0[192,64] / sqrt(192) + b0
        #pragma unroll 4
        for (int i = 0; i < 64; i++) {
            acc += c[i]       * __ldg(&W0[i * 64 + t]);
            acc += c[240 + i] * __ldg(&W0[(64 + i) * 64 + t]);
            acc += c[480 + i] * __ldg(&W0[(128 + i) * 64 + t]);
        }
        out[(size_t)g * FEAT + t] = acc * rsqrtf(192.f) + __ldg(&b0[t]);
    } else if (t < 160) {
        // group 1o: cat[96,3] @ W1[96,32] / sqrt(96)
        int cc = t - 64, o = cc / 3, dd = cc % 3;
        #pragma unroll 4
        for (int i = 0; i < 32; i++) {
            acc += c[64 + i * 3 + dd]       * __ldg(&W1[i * 32 + o]);
            acc += c[240 + 64 + i * 3 + dd] * __ldg(&W1[(32 + i) * 32 + o]);
            acc += c[480 + 64 + i * 3 + dd] * __ldg(&W1[(64 + i) * 32 + o]);
        }
        out[(size_t)g * FEAT + t] = acc * rsqrtf(96.f);
    } else {
        // group 2e: cat[48,5] @ W2[48,16] / sqrt(48)
        int cc = t - 160, o = cc / 5, dd = cc % 5;
        #pragma unroll 4
        for (int i = 0; i < 16; i++) {
            acc += c[160 + i * 5 + dd]       * __ldg(&W2[i * 16 + o]);
            acc += c[240 + 160 + i * 5 + dd] * __ldg(&W2[(16 + i) * 16 + o]);
            acc += c[480 + 160 + i * 5 + dd] * __ldg(&W2[(32 + i) * 16 + o]);
        }
        out[(size_t)g * FEAT + t] = acc * rsqrtf(48.f);
    }
}

// ---------------------------------------------------------------------------
// Launch
// ---------------------------------------------------------------------------
extern "C" void kernel_launch(void* const* d_in, const int* in_sizes, int n_in,
                              void* d_out, int out_size)
{
    const float* x     = nullptr;
    const int*   index = nullptr;
    const float *W0 = nullptr, *W1 = nullptr, *W2 = nullptr, *b0 = nullptr;

    for (int i = 0; i < n_in; i++) {
        switch (in_sizes[i]) {
            case 96000000: x     = (const float*)d_in[i]; break;
            case 400000:   index = (const int*)  d_in[i]; break;
            case 12288:    W0    = (const float*)d_in[i]; break;
            case 3072:     W1    = (const float*)d_in[i]; break;
            case 768:      W2    = (const float*)d_in[i]; break;
            case 64:       b0    = (const float*)d_in[i]; break;
            default: break;  // dim_size scalar etc.
        }
    }

    float* out = (float*)d_out;
    (void)out_size;

    k_zero   <<<(N_GRAPHS + 255) / 256, 256>>>();
    k_hist   <<<(N_NODES + 255) / 256, 256>>>(index);
    k_scan   <<<1, 1024>>>();
    k_scatter<<<(N_NODES + 255) / 256, 256>>>(index);
    k_pool   <<<N_GRAPHS, 256>>>(x, W0, W1, W2, b0, out);
}